// round 3
// baseline (speedup 1.0000x reference)
#include <cuda_runtime.h>
#include <cstdint>

// Problem constants (fixed by the dataset)
#define B_      2
#define L_      1024
#define D_EMB   64
#define D_MOD   128     // output channels
#define D_IN    129     // 64 + 64 + 1

#define TI 8            // i-rows per block
#define TJ 64           // j-cols per block

// Scratch (no cudaMalloc allowed): precomputed per-row projections.
__device__ float g_ub[B_ * L_ * D_MOD];   // left-proj + bias
__device__ float g_v [B_ * L_ * D_MOD];   // right-proj
__device__ float g_wt[D_EMB * 2 * D_MOD]; // W transposed: wt[c*128 + d] = W[d, c], c in [0,128)
__device__ float g_wl[D_MOD];             // W[:,128] (seqsep column)

// Streaming 128-bit store: evict-first in L2 (output is 8.5x L2 capacity).
__device__ __forceinline__ void stg_cs_v4(float4* p, float4 v) {
    asm volatile("st.global.cs.v4.f32 [%0], {%1,%2,%3,%4};"
                 :: "l"(p), "f"(v.x), "f"(v.y), "f"(v.z), "f"(v.w) : "memory");
}

// ---------------------------------------------------------------------------
// Kernel 1: repack W (row-major [128,129]) into transposed form + seqsep col.
// ---------------------------------------------------------------------------
__global__ void prep_w_kernel(const float* __restrict__ W) {
    int t = blockIdx.x * blockDim.x + threadIdx.x;
    if (t < D_MOD * D_IN) {
        int d = t / D_IN;
        int c = t - d * D_IN;
        float w = W[t];
        if (c == D_MOD) g_wl[d] = w;        // c == 128
        else            g_wt[c * D_MOD + d] = w;
    }
}

// ---------------------------------------------------------------------------
// Kernel 2: per-row projections.
//   ub[bl,d] = bias[d] + sum_c W[d,c]    * e[bl,c]
//   v [bl,d] =           sum_c W[d,64+c] * e[bl,c]
// One block per (b,l), 128 threads (one per d). e row staged in smem,
// W read transposed -> fully coalesced across d. W columns loaded through
// __ldg on a restrict alias so ptxas can batch the 128 loads (MLP).
// ---------------------------------------------------------------------------
__global__ void __launch_bounds__(D_MOD) prep_uv_kernel(
    const int* __restrict__ seq,
    const float* __restrict__ emb,
    const float* __restrict__ bias)
{
    int bl = blockIdx.x;          // 0 .. B*L-1
    int d  = threadIdx.x;         // 0 .. 127
    __shared__ float e[D_EMB];
    if (d < D_EMB) e[d] = emb[seq[bl] * D_EMB + d];
    __syncthreads();

    const float* __restrict__ wt = g_wt;

    float u = bias[d];
    float v = 0.0f;
#pragma unroll
    for (int c = 0; c < D_EMB; ++c) {
        float ec = e[c];
        u = fmaf(__ldg(wt + c * D_MOD + d),           ec, u);
        v = fmaf(__ldg(wt + (D_EMB + c) * D_MOD + d), ec, v);
    }
    g_ub[bl * D_MOD + d] = u;
    g_v [bl * D_MOD + d] = v;
}

// ---------------------------------------------------------------------------
// Kernel 3: main pair kernel. Block = one (b, i-tile of 8, j-tile of 64).
// out[b,i,j,:] = ub[b,i,:] + v[b,j,:] + wl[:] * log(|idx_i - idx_j|+1)
// Pure HBM-write-bound: 1 FADD + 1 FMA per output float.
// smem: ub tile 4KB, v tile 32KB, s tile 2KB, wl 0.5KB  (~38.7KB/block)
// ---------------------------------------------------------------------------
__global__ void __launch_bounds__(256) pair_main_kernel(
    const int* __restrict__ idx,
    float* __restrict__ out)
{
    const int b  = blockIdx.z;
    const int i0 = blockIdx.y * TI;
    const int j0 = blockIdx.x * TJ;

    __shared__ float s_ub[TI * D_MOD];
    __shared__ float s_v [TJ * D_MOD];
    __shared__ float s_s [TI * TJ];
    __shared__ float s_wl[D_MOD];

    const int t = threadIdx.x;

    // Stage ub tile: 8*128 = 1024 floats = 256 float4 (1 per thread)
    {
        const float4* ubg = (const float4*)(g_ub + ((size_t)b * L_ + i0) * D_MOD);
        ((float4*)s_ub)[t] = ubg[t];
    }
    // Stage v tile: 64*128 = 8192 floats = 2048 float4 (8 per thread)
    {
        const float4* vg = (const float4*)(g_v + ((size_t)b * L_ + j0) * D_MOD);
#pragma unroll
        for (int k = 0; k < 8; ++k)
            ((float4*)s_v)[t + k * 256] = vg[t + k * 256];
    }
    // Stage wl: 128 floats = 32 float4
    if (t < 32) ((float4*)s_wl)[t] = ((const float4*)g_wl)[t];

    // Stage seqsep tile: 512 values, 2 per thread
#pragma unroll
    for (int k = 0; k < 2; ++k) {
        int cell = t + k * 256;
        int i = cell >> 6;        // / TJ
        int j = cell & (TJ - 1);
        int di = idx[b * L_ + i0 + i] - idx[b * L_ + j0 + j];
        s_s[cell] = logf(fabsf((float)di) + 1.0f);
    }
    __syncthreads();

    // Warp layout: row = warp id (one i per warp), lanes cover d in float4s.
    const int dg  = t & 31;       // d-group: d = dg*4
    const int row = t >> 5;       // i within tile (0..7)

    const float4 ub4 = ((const float4*)(s_ub + row * D_MOD))[dg];
    const float4 wl4 = ((const float4*)s_wl)[dg];
    const float* ss  = s_s + row * TJ;

    float4* orow = (float4*)(out +
        (((size_t)(b * L_ + i0 + row)) * L_ + j0) * D_MOD) + dg;

#pragma unroll 8
    for (int j = 0; j < TJ; ++j) {
        float s = ss[j];
        float4 v4 = ((const float4*)(s_v + j * D_MOD))[dg];
        float4 o;
        o.x = fmaf(wl4.x, s, ub4.x + v4.x);
        o.y = fmaf(wl4.y, s, ub4.y + v4.y);
        o.z = fmaf(wl4.z, s, ub4.z + v4.z);
        o.w = fmaf(wl4.w, s, ub4.w + v4.w);
        stg_cs_v4(orow + j * (D_MOD / 4), o);
    }
}

// ---------------------------------------------------------------------------
// Launch. Inputs (metadata order): seq i32[2,1024], idx i32[2,1024],
// emb_table f32[21,64], W f32[128,129], b f32[128]. Output f32[2,1024,1024,128].
// ---------------------------------------------------------------------------
extern "C" void kernel_launch(void* const* d_in, const int* in_sizes, int n_in,
                              void* d_out, int out_size)
{
    const int*   seq  = (const int*)  d_in[0];
    const int*   idx  = (const int*)  d_in[1];
    const float* emb  = (const float*)d_in[2];
    const float* W    = (const float*)d_in[3];
    const float* bias = (const float*)d_in[4];
    float*       out  = (float*)d_out;

    (void)in_sizes; (void)n_in; (void)out_size;

    // 1) repack W
    prep_w_kernel<<<(D_MOD * D_IN + 255) / 256, 256>>>(W);

    // 2) per-row projections
    prep_uv_kernel<<<B_ * L_, D_MOD>>>(seq, emb, bias);

    // 3) main pair kernel
    dim3 grid(L_ / TJ, L_ / TI, B_);   // (16, 128, 2) = 4096 blocks
    pair_main_kernel<<<grid, 256>>>(idx, out);
}

// round 11
// speedup vs baseline: 1.0100x; 1.0100x over previous
#include <cuda_runtime.h>
#include <cstdint>

// Problem constants (fixed by the dataset)
#define B_      2
#define L_      1024
#define D_SEQ   21
#define D_EMB   64
#define D_MOD   128     // output channels
#define D_IN    129     // 64 + 64 + 1

#define TI 8            // i-rows per block
#define TJ 64           // j-cols per block

// Scratch (no cudaMalloc allowed): tiny projection tables.
// U[s,d] = bias[d] + sum_c emb[s,c] * W[d,c]        (left half + bias)
// V[s,d] =           sum_c emb[s,c] * W[d,64+c]     (right half)
__device__ float g_U [D_SEQ * D_MOD];
__device__ float g_V [D_SEQ * D_MOD];
__device__ float g_wl[D_MOD];             // W[:,128] (seqsep column)

// Streaming 128-bit store: evict-first in L2 (output is 8.5x L2 capacity).
__device__ __forceinline__ void stg_cs_v4(float4* p, float4 v) {
    asm volatile("st.global.cs.v4.f32 [%0], {%1,%2,%3,%4};"
                 :: "l"(p), "f"(v.x), "f"(v.y), "f"(v.z), "f"(v.w) : "memory");
}

// ---------------------------------------------------------------------------
// Kernel 1: build the 21-row projection tables. One block per table row s,
// 128 threads (one per output channel d). 344 KFLOP total — microseconds.
// ---------------------------------------------------------------------------
__global__ void __launch_bounds__(D_MOD) prep_tables_kernel(
    const float* __restrict__ W,
    const float* __restrict__ emb,
    const float* __restrict__ bias)
{
    const int s = blockIdx.x;     // 0 .. 20
    const int d = threadIdx.x;    // 0 .. 127

    __shared__ float e[D_EMB];
    if (d < D_EMB) e[d] = emb[s * D_EMB + d];
    __syncthreads();

    const float* __restrict__ wrow = W + d * D_IN;   // W[d, :]
    float u = bias[d];
    float v = 0.0f;
#pragma unroll
    for (int c = 0; c < D_EMB; ++c) {
        u = fmaf(__ldg(wrow + c),         e[c], u);
        v = fmaf(__ldg(wrow + D_EMB + c), e[c], v);
    }
    g_U[s * D_MOD + d] = u;
    g_V[s * D_MOD + d] = v;
    if (s == 0) g_wl[d] = __ldg(wrow + 2 * D_EMB);   // W[d,128]
}

// ---------------------------------------------------------------------------
// Kernel 2: main pair kernel. Block = one (b, i-tile of 8, j-tile of 64).
// out[b,i,j,:] = U[seq_i,:] + V[seq_j,:] + wl[:] * log(|idx_i - idx_j|+1)
// Pure HBM-write-bound: 1 FADD + 1 FMA per output float.
// smem: U 10.5K + V 10.5K + s 2K + wl 0.5K + seq ~0.3K  (~24.5 KB/block)
// ---------------------------------------------------------------------------
__global__ void __launch_bounds__(256) pair_main_kernel(
    const int* __restrict__ idx,
    const int* __restrict__ seq,
    float* __restrict__ out)
{
    const int b  = blockIdx.z;
    const int i0 = blockIdx.y * TI;
    const int j0 = blockIdx.x * TJ;

    __shared__ float s_U [D_SEQ * D_MOD];   // 2688 floats
    __shared__ float s_V [D_SEQ * D_MOD];
    __shared__ float s_s [TI * TJ];
    __shared__ float s_wl[D_MOD];
    __shared__ int   s_seqi[TI];
    __shared__ int   s_seqj[TJ];

    const int t = threadIdx.x;

    // Stage U,V tables: 672 float4 each, 256 threads -> 3 strided passes.
    {
        const float4* Ug = (const float4*)g_U;
        const float4* Vg = (const float4*)g_V;
#pragma unroll
        for (int k = 0; k < 3; ++k) {
            int p = t + k * 256;
            if (p < (D_SEQ * D_MOD) / 4) {
                ((float4*)s_U)[p] = Ug[p];
                ((float4*)s_V)[p] = Vg[p];
            }
        }
    }
    if (t < D_MOD / 4) ((float4*)s_wl)[t] = ((const float4*)g_wl)[t];
    if (t < TI) s_seqi[t] = seq[b * L_ + i0 + t];
    if (t < TJ) s_seqj[t] = seq[b * L_ + j0 + t];

    // Stage seqsep tile: 512 values, 2 per thread (idx reads hit L1).
#pragma unroll
    for (int k = 0; k < 2; ++k) {
        int cell = t + k * 256;
        int i = cell >> 6;        // / TJ
        int j = cell & (TJ - 1);
        int di = idx[b * L_ + i0 + i] - idx[b * L_ + j0 + j];
        s_s[cell] = logf(fabsf((float)di) + 1.0f);
    }
    __syncthreads();

    // Warp layout: row = warp id (one i per warp), lanes cover d in float4s.
    const int dg  = t & 31;       // d-group: d = dg*4
    const int row = t >> 5;       // i within tile (0..7)

    const float4 ub4 = ((const float4*)(s_U + s_seqi[row] * D_MOD))[dg];
    const float4 wl4 = ((const float4*)s_wl)[dg];
    const float* ss  = s_s + row * TJ;

    float4* orow = (float4*)(out +
        (((size_t)(b * L_ + i0 + row)) * L_ + j0) * D_MOD) + dg;

#pragma unroll 8
    for (int j = 0; j < TJ; ++j) {
        float s = ss[j];
        float4 v4 = ((const float4*)(s_V + s_seqj[j] * D_MOD))[dg];
        float4 o;
        o.x = fmaf(wl4.x, s, ub4.x + v4.x);
        o.y = fmaf(wl4.y, s, ub4.y + v4.y);
        o.z = fmaf(wl4.z, s, ub4.z + v4.z);
        o.w = fmaf(wl4.w, s, ub4.w + v4.w);
        stg_cs_v4(orow + j * (D_MOD / 4), o);
    }
}

// ---------------------------------------------------------------------------
// Launch. Inputs (metadata order): seq i32[2,1024], idx i32[2,1024],
// emb_table f32[21,64], W f32[128,129], b f32[128]. Output f32[2,1024,1024,128].
// ---------------------------------------------------------------------------
extern "C" void kernel_launch(void* const* d_in, const int* in_sizes, int n_in,
                              void* d_out, int out_size)
{
    const int*   seq  = (const int*)  d_in[0];
    const int*   idx  = (const int*)  d_in[1];
    const float* emb  = (const float*)d_in[2];
    const float* W    = (const float*)d_in[3];
    const float* bias = (const float*)d_in[4];
    float*       out  = (float*)d_out;

    (void)in_sizes; (void)n_in; (void)out_size;

    // 1) build 21-row projection tables
    prep_tables_kernel<<<D_SEQ, D_MOD>>>(W, emb, bias);

    // 2) main pair kernel
    dim3 grid(L_ / TJ, L_ / TI, B_);   // (16, 128, 2) = 4096 blocks
    pair_main_kernel<<<grid, 256>>>(idx, seq, out);
}